// round 15
// baseline (speedup 1.0000x reference)
#include <cuda_runtime.h>
#include <math.h>

// Fixed shapes
#define BB   64
#define TTT  256
#define SST  1024
#define HHH  512
#define EEE  512
#define VVV  32
#define G3   1536
#define OOO  31
#define NCH  8
#define CHS  128

// ---------------- scratch (static device globals; no allocation) ----------
__device__ float g_GiT [VVV * G3];            // gi table (embed@W_ih^T + b_ih)
__device__ float g_WhhT[HHH * G3];            // W_hh^T  [k][j]   (3MB)
__device__ float g_fcWT[2 * HHH * 32];        // fc_W^T  [d][o]   (o padded to 32)
__device__ float g_h   [2][BB * HHH];         // ping-pong hidden
__device__ float g_gh  [2][BB * G3];          // ping-pong h@W_hh^T (pre-bias)
__device__ float g_pm  [2][BB * NCH];         // ping-pong chunk softmax max
__device__ float g_pl  [2][BB * NCH];         // ping-pong chunk softmax denom
__device__ float g_pctx[2][BB * NCH * HHH];   // ping-pong chunk unnorm ctx

// ---------------- helpers -------------------------------------------------
__device__ __forceinline__ float dot4(float4 a, float4 b) {
    return a.x*b.x + a.y*b.y + a.z*b.z + a.w*b.w;
}
__device__ __forceinline__ float wsum(float v) {
    #pragma unroll
    for (int o = 16; o; o >>= 1) v += __shfl_xor_sync(0xffffffffu, v, o);
    return v;
}
// PyTorch GRU cell (b_ih folded into gi table; b_hh added here)
__device__ __forceinline__ float gru_h(int j, const float* __restrict__ gi,
                                       const float* __restrict__ gh,
                                       const float* __restrict__ bhh, float hp) {
    float r = 1.f / (1.f + expf(-(gi[j]        + gh[j]        + bhh[j])));
    float z = 1.f / (1.f + expf(-(gi[j+HHH]    + gh[j+HHH]    + bhh[j+HHH])));
    float n = tanhf(gi[j+2*HHH] + r * (gh[j+2*HHH] + bhh[j+2*HHH]));
    return (1.f - z) * n + z * hp;
}

// ---------------- one-time prep kernels -----------------------------------
// Whh [1536][512] -> WhhT [512][1536], 32x32 smem tile transpose.
__global__ void k_transpose(const float* __restrict__ Whh) {
    __shared__ float tile[32][33];
    int kx = blockIdx.x * 32;   // k tile (16 tiles)
    int jy = blockIdx.y * 32;   // j tile (48 tiles)
    int tx = threadIdx.x, ty = threadIdx.y;
    #pragma unroll
    for (int i = 0; i < 32; i += 8)
        tile[ty + i][tx] = Whh[(size_t)(jy + ty + i) * HHH + kx + tx];   // coalesced k
    __syncthreads();
    #pragma unroll
    for (int i = 0; i < 32; i += 8)
        g_WhhT[(size_t)(kx + ty + i) * G3 + jy + tx] = tile[tx][ty + i]; // coalesced j
}
// fcW [31][1024] -> fcWT [1024][32] (zero pad col 31)
__global__ void k_fcT(const float* __restrict__ fcW) {
    int idx = blockIdx.x * 512 + threadIdx.x;   // 64 x 512 = 32768
    int d = idx >> 5, o = idx & 31;
    g_fcWT[idx] = (o < OOO) ? fcW[(size_t)o * (2*HHH) + d] : 0.f;
}
// GiTable[v][j] = dot(embed[v], W_ih[j]) + b_ih[j]
__global__ void k_gitable(const float* __restrict__ embed,
                          const float* __restrict__ Wih,
                          const float* __restrict__ bih) {
    int gw   = (blockIdx.x * blockDim.x + threadIdx.x) >> 5;
    int lane = threadIdx.x & 31;
    if (gw >= G3) return;
    const float4* wr = (const float4*)(Wih + (size_t)gw * EEE);
    float4 w0 = wr[lane], w1 = wr[lane+32], w2 = wr[lane+64], w3 = wr[lane+96];
    float bj = bih[gw];
    for (int v = 0; v < VVV; v++) {
        const float4* er = (const float4*)(embed + (size_t)v * EEE);
        float acc = dot4(w0,er[lane]) + dot4(w1,er[lane+32])
                  + dot4(w2,er[lane+64]) + dot4(w3,er[lane+96]);
        acc = wsum(acc);
        if (lane == 0) g_GiT[v * G3 + gw] = acc + bj;
    }
}

// ---------------- gh GEMM body: gh[b][j] = sum_k h[b][k] * WhhT[k][j] -----
// 256 threads: lane jq (32) -> 4 consecutive j via float4; warp w -> 1 batch.
// Output-stationary, NO reductions. Block tile: 128 j x 8 b, full k=512.
__device__ __forceinline__ void gh_gemm(const float* __restrict__ sh,  // [8][512]
                                        int jt, int bt, float* __restrict__ out) {
    int tid = threadIdx.x;
    int jq = tid & 31, bi = tid >> 5;
    const float4* W4 = (const float4*)g_WhhT;
    const float4* h4 = (const float4*)(sh + bi * HHH);
    int jcol = jt * 32 + jq;                  // float4 column in [0,384)
    float4 acc = {0.f, 0.f, 0.f, 0.f};
    #pragma unroll 2
    for (int k4 = 0; k4 < 128; k4++) {
        float4 hv = h4[k4];
        float4 w0 = W4[(size_t)(k4*4+0) * 384 + jcol];
        float4 w1 = W4[(size_t)(k4*4+1) * 384 + jcol];
        float4 w2 = W4[(size_t)(k4*4+2) * 384 + jcol];
        float4 w3 = W4[(size_t)(k4*4+3) * 384 + jcol];
        acc.x += hv.x*w0.x + hv.y*w1.x + hv.z*w2.x + hv.w*w3.x;
        acc.y += hv.x*w0.y + hv.y*w1.y + hv.z*w2.y + hv.w*w3.y;
        acc.z += hv.x*w0.z + hv.y*w1.z + hv.z*w2.z + hv.w*w3.z;
        acc.w += hv.x*w0.w + hv.y*w1.w + hv.z*w2.w + hv.w*w3.w;
    }
    ((float4*)(out + (size_t)(bt*8 + bi) * G3))[jcol] = acc;
}

// initial gh for t=0 from hlast. grid 96 = 12 jt x 8 bt
__global__ void k1_pro(const float* __restrict__ hlast) {
    __shared__ float sh[8 * HHH];
    int jt = blockIdx.x % 12, bt = blockIdx.x / 12;
    const float4* src = (const float4*)(hlast + (size_t)bt * 8 * HHH);
    for (int i = threadIdx.x; i < 8 * HHH / 4; i += 256) ((float4*)sh)[i] = src[i];
    __syncthreads();
    gh_gemm(sh, jt, bt, g_gh[0]);
}

// ---------------- fc body (combine chunk partials + fc head) --------------
// For step tau: reads g_h[(tau+1)&1], partials[tau&1]; writes out[:, tau, :].
__device__ __forceinline__ void fc_body(int b, int tau, float* smem,
                                        const int* __restrict__ tlen,
                                        const float* __restrict__ fcb,
                                        float* __restrict__ out) {
    int tid = threadIdx.x;
    int par = tau & 1;
    float* cat  = smem;          // [0..1023]  = [h_new ; ctx]
    float* part = smem + 1024;   // [8][32]
    float pm[NCH], pl[NCH];
    #pragma unroll
    for (int k = 0; k < NCH; k++) { pm[k] = g_pm[par][b*NCH+k]; pl[k] = g_pl[par][b*NCH+k]; }
    float M = pm[0];
    #pragma unroll
    for (int k = 1; k < NCH; k++) M = fmaxf(M, pm[k]);
    float wk[NCH], L = 0.f;
    #pragma unroll
    for (int k = 0; k < NCH; k++) { wk[k] = expf(pm[k] - M); L += pl[k] * wk[k]; }
    float invL = 1.f / L;
    const float* hn = &g_h[(tau + 1) & 1][(size_t)b * HHH];
    for (int d = tid; d < HHH; d += 256) {
        cat[d] = hn[d];
        float s = 0.f;
        #pragma unroll
        for (int k = 0; k < NCH; k++)
            s += wk[k] * g_pctx[par][((size_t)b * NCH + k) * HHH + d];
        cat[HHH + d] = s * invL;
    }
    __syncthreads();
    int o = tid & 31, dg = tid >> 5;
    float acc = 0.f;
    #pragma unroll 4
    for (int dd = 0; dd < 128; dd++) {
        int d = dg * 128 + dd;
        acc += g_fcWT[d * 32 + o] * cat[d];    // LDG coalesced, LDS broadcast
    }
    part[dg * 32 + o] = acc;
    __syncthreads();
    if (tid < 32) {
        float s = 0.f;
        #pragma unroll
        for (int k = 0; k < 8; k++) s += part[k * 32 + tid];
        if (tid < OOO)
            out[((size_t)b * TTT + tau) * OOO + tid] =
                (tau < tlen[b]) ? (s + fcb[tid]) : 0.0f;
    }
}

// ---------------- the fused per-step kernel --------------------------------
// grid 672: [0,64)   fc for step t-1          (previous kernel ordered it)
//           [64,160) gh GEMM for step t+1     (recomputes h(t+1) locally)
//           [160,672) attention for step t    (64 b x 8 chunks)
__global__ __launch_bounds__(256)
void k2(const float* __restrict__ enc,  const float* __restrict__ hlast,
        const float* __restrict__ bhh,  const int* __restrict__ trg,
        const int* __restrict__ slen,   const int* __restrict__ tlen,
        const float* __restrict__ fcb,  float* __restrict__ out, int t) {
    __shared__ float smem[4624];
    int bid = blockIdx.x, tid = threadIdx.x;

    if (bid < 64) {                       // ---- fc for previous step ----
        if (t == 0) return;
        fc_body(bid, t - 1, smem, tlen, fcb, out);
        return;
    }
    if (bid < 160) {                      // ---- gh for next step ----
        int g = bid - 64, jt = g % 12, bt = g / 12;
        float* sh = smem;                 // [8][512]
        const float* ghin = g_gh[t & 1];
        for (int idx = tid; idx < 8 * HHH; idx += 256) {
            int bl = idx >> 9, j = idx & (HHH - 1);
            int b  = bt * 8 + bl;
            const float* gi = g_GiT + (size_t)trg[b * TTT + t] * G3;
            const float* gh = ghin + (size_t)b * G3;
            float hp = (t == 0) ? hlast[(size_t)b * HHH + j]
                                : g_h[t & 1][(size_t)b * HHH + j];
            sh[idx] = gru_h(j, gi, gh, bhh, hp);
        }
        __syncthreads();
        gh_gemm(sh, jt, bt, g_gh[(t + 1) & 1]);
        return;
    }

    // ---- attention ----
    int a = bid - 160, b = a >> 3, c = a & 7;
    int par = t & 1;
    int sl = slen[b];
    float* sh_h = smem;                                   // 512
    float (*sm_ctx)[HHH] = (float(*)[HHH])(smem + 512);   // 8 x 512
    float* sm_m = smem + 512 + 4096;
    float* sm_l = sm_m + 8;

    if (c * CHS >= sl) {                  // dead chunk (c>0): zero partials
        for (int d = tid; d < HHH; d += 256)
            g_pctx[par][((size_t)b * NCH + c) * HHH + d] = 0.f;
        if (tid == 0) { g_pm[par][b*NCH+c] = -1e30f; g_pl[par][b*NCH+c] = 0.f; }
        return;
    }

    {   // gates -> h_new
        const float* gi = g_GiT + (size_t)trg[b * TTT + t] * G3;
        const float* gh = g_gh[t & 1] + (size_t)b * G3;
        for (int j = tid; j < HHH; j += 256) {
            float hp = (t == 0) ? hlast[(size_t)b * HHH + j]
                                : g_h[t & 1][(size_t)b * HHH + j];
            float hn = gru_h(j, gi, gh, bhh, hp);
            sh_h[j] = hn;
            if (c == 0) g_h[(t + 1) & 1][(size_t)b * HHH + j] = hn;
        }
    }
    __syncthreads();

    // online softmax, 2 rows per iteration (pipelined shuffle reductions)
    int w = tid >> 5, lane = tid & 31;
    const float4* hv = (const float4*)sh_h;
    float4 h0 = hv[lane], h1 = hv[lane+32], h2 = hv[lane+64], h3 = hv[lane+96];
    float m = -1e30f, l = 0.f;
    float4 c0 = {0,0,0,0}, c1 = {0,0,0,0}, c2 = {0,0,0,0}, c3 = {0,0,0,0};
    int s0 = c * CHS + w * 16;
    #pragma unroll 1
    for (int i = 0; i < 16; i += 2) {
        int s = s0 + i;
        if (s >= sl) break;                              // warp-uniform
        const float4* ea = (const float4*)(enc + ((size_t)b * SST + s) * HHH);
        float4 a0 = ea[lane], a1 = ea[lane+32], a2 = ea[lane+64], a3 = ea[lane+96];
        float dA = wsum(dot4(a0,h0) + dot4(a1,h1) + dot4(a2,h2) + dot4(a3,h3));
        float4 b0 = {0,0,0,0}, b1 = {0,0,0,0}, b2 = {0,0,0,0}, b3 = {0,0,0,0};
        float dB = -1e30f;
        if (s + 1 < sl) {                                // warp-uniform
            const float4* eb = (const float4*)(enc + ((size_t)b * SST + s + 1) * HHH);
            b0 = eb[lane]; b1 = eb[lane+32]; b2 = eb[lane+64]; b3 = eb[lane+96];
            dB = wsum(dot4(b0,h0) + dot4(b1,h1) + dot4(b2,h2) + dot4(b3,h3));
        }
        float mn   = fmaxf(m, fmaxf(dA, dB));
        float corr = expf(m - mn);
        float pA   = expf(dA - mn);
        float pB   = expf(dB - mn);                      // exp(-1e30-mn) == 0
        l = l * corr + pA + pB;
        c0.x = c0.x*corr + pA*a0.x + pB*b0.x;  c0.y = c0.y*corr + pA*a0.y + pB*b0.y;
        c0.z = c0.z*corr + pA*a0.z + pB*b0.z;  c0.w = c0.w*corr + pA*a0.w + pB*b0.w;
        c1.x = c1.x*corr + pA*a1.x + pB*b1.x;  c1.y = c1.y*corr + pA*a1.y + pB*b1.y;
        c1.z = c1.z*corr + pA*a1.z + pB*b1.z;  c1.w = c1.w*corr + pA*a1.w + pB*b1.w;
        c2.x = c2.x*corr + pA*a2.x + pB*b2.x;  c2.y = c2.y*corr + pA*a2.y + pB*b2.y;
        c2.z = c2.z*corr + pA*a2.z + pB*b2.z;  c2.w = c2.w*corr + pA*a2.w + pB*b2.w;
        c3.x = c3.x*corr + pA*a3.x + pB*b3.x;  c3.y = c3.y*corr + pA*a3.y + pB*b3.y;
        c3.z = c3.z*corr + pA*a3.z + pB*b3.z;  c3.w = c3.w*corr + pA*a3.w + pB*b3.w;
        m = mn;
    }
    if (lane == 0) { sm_m[w] = m; sm_l[w] = l; }
    __syncthreads();
    float M = sm_m[0];
    #pragma unroll
    for (int k = 1; k < 8; k++) M = fmaxf(M, sm_m[k]);
    float L = 0.f;
    #pragma unroll
    for (int k = 0; k < 8; k++) L += sm_l[k] * expf(sm_m[k] - M);
    float f = expf(m - M);                               // 0 for empty warps
    c0.x*=f; c0.y*=f; c0.z*=f; c0.w*=f;  c1.x*=f; c1.y*=f; c1.z*=f; c1.w*=f;
    c2.x*=f; c2.y*=f; c2.z*=f; c2.w*=f;  c3.x*=f; c3.y*=f; c3.z*=f; c3.w*=f;
    float4* cw = (float4*)(sm_ctx[w]);
    cw[lane] = c0; cw[lane+32] = c1; cw[lane+64] = c2; cw[lane+96] = c3;
    __syncthreads();
    for (int d = tid; d < HHH; d += 256) {
        float s = 0.f;
        #pragma unroll
        for (int k = 0; k < 8; k++) s += sm_ctx[k][d];
        g_pctx[par][((size_t)b * NCH + c) * HHH + d] = s;
    }
    if (tid == 0) { g_pm[par][b*NCH+c] = M; g_pl[par][b*NCH+c] = L; }
}

// final fc for t = 255
__global__ void k_fc_final(const int* __restrict__ tlen,
                           const float* __restrict__ fcb,
                           float* __restrict__ out) {
    __shared__ float smem[1280];
    fc_body(blockIdx.x, TTT - 1, smem, tlen, fcb, out);
}

// ---------------- launch ---------------------------------------------------
extern "C" void kernel_launch(void* const* d_in, const int* in_sizes, int n_in,
                              void* d_out, int out_size) {
    const int*   trg   = (const int*)  d_in[0];
    const int*   tlen  = (const int*)  d_in[1];
    const int*   slen  = (const int*)  d_in[2];
    const float* enc   = (const float*)d_in[3];
    const float* hlast = (const float*)d_in[4];
    const float* embed = (const float*)d_in[5];
    const float* Wih   = (const float*)d_in[6];
    const float* Whh   = (const float*)d_in[7];
    const float* bih   = (const float*)d_in[8];
    const float* bhh   = (const float*)d_in[9];
    const float* fcW   = (const float*)d_in[10];
    const float* fcb   = (const float*)d_in[11];
    float*       out   = (float*)d_out;

    k_transpose<<<dim3(16, 48), dim3(32, 8)>>>(Whh);
    k_fcT      <<<64, 512>>>(fcW);
    k_gitable  <<<192, 256>>>(embed, Wih, bih);
    k1_pro     <<<96, 256>>>(hlast);
    for (int t = 0; t < TTT; t++)
        k2<<<672, 256>>>(enc, hlast, bhh, trg, slen, tlen, fcb, out, t);
    k_fc_final<<<64, 256>>>(tlen, fcb, out);
}